// round 4
// baseline (speedup 1.0000x reference)
#include <cuda_runtime.h>
#include <cuda_fp16.h>

#define NLAYERS 32
#define RPT 8               // rows per thread
#define NPAIR (RPT / 2)
#define CLIPV 5.0f

__device__ __forceinline__ float clip5(float v) {
    return fminf(fmaxf(v, -CLIPV), CLIPV);
}

// tanh.approx.f16x2: ONE MUFU op -> TWO tanh evaluations.
__device__ __forceinline__ __half2 tanh2(__half2 v) {
    unsigned r, a = *reinterpret_cast<unsigned*>(&v);
    asm("tanh.approx.f16x2 %0, %1;" : "=r"(r) : "r"(a));
    return *reinterpret_cast<__half2*>(&r);
}

__global__ void __launch_bounds__(256) fraud_kernel(
    const float* __restrict__ x,      // [B,2]
    const float* __restrict__ W,      // [32,2,2]
    const float* __restrict__ b,      // [32,2]
    const float* __restrict__ scale,  // [32,2]
    const float* __restrict__ shift,  // [32,2]
    const float* __restrict__ Wo,     // [1,2]
    const float* __restrict__ bo,     // [1]
    float* __restrict__ out,          // [B,1]
    int nrows)
{
    // Fused: a_{l+1} = M_l * tanh(a_l) + c_l, with
    //   M_l = clip(W_{l+1}) * diag(scale_l),  c_l = clip(W_{l+1})@shift_l + clip(b_{l+1})
    // All broadcast into half2 lanes. Head kept in f32.
    __shared__ __half2 sM[NLAYERS - 1][4];   // M00,M01,M10,M11
    __shared__ __half2 sC[NLAYERS - 1][2];   // C0,C1
    __shared__ __half2 sL0[6];               // W00,W01,W10,W11,B0,B1 (layer 0, unclipped)
    __shared__ float   sF[3];                // v0, v1, c_out (f32 head)

    const int t = threadIdx.x;
    if (t < NLAYERS - 1) {
        float4 w = reinterpret_cast<const float4*>(W)[t + 1];
        w.x = clip5(w.x); w.y = clip5(w.y); w.z = clip5(w.z); w.w = clip5(w.w);
        float bb0 = clip5(b[2 * (t + 1)]);
        float bb1 = clip5(b[2 * (t + 1) + 1]);
        float s0 = scale[2 * t], s1 = scale[2 * t + 1];
        float h0 = shift[2 * t], h1 = shift[2 * t + 1];
        sM[t][0] = __float2half2_rn(w.x * s0);
        sM[t][1] = __float2half2_rn(w.y * s1);
        sM[t][2] = __float2half2_rn(w.z * s0);
        sM[t][3] = __float2half2_rn(w.w * s1);
        sC[t][0] = __float2half2_rn(fmaf(w.x, h0, fmaf(w.y, h1, bb0)));
        sC[t][1] = __float2half2_rn(fmaf(w.z, h0, fmaf(w.w, h1, bb1)));
    } else if (t == NLAYERS - 1) {
        float s0 = scale[2 * 31], s1 = scale[2 * 31 + 1];
        float h0 = shift[2 * 31], h1 = shift[2 * 31 + 1];
        sF[0] = Wo[0] * s0;
        sF[1] = Wo[1] * s1;
        sF[2] = fmaf(Wo[0], h0, fmaf(Wo[1], h1, bo[0]));
    } else if (t == NLAYERS) {
        float4 w = reinterpret_cast<const float4*>(W)[0];  // layer 0: no clip
        sL0[0] = __float2half2_rn(w.x);
        sL0[1] = __float2half2_rn(w.y);
        sL0[2] = __float2half2_rn(w.z);
        sL0[3] = __float2half2_rn(w.w);
        sL0[4] = __float2half2_rn(b[0]);
        sL0[5] = __float2half2_rn(b[1]);
    }
    __syncthreads();

    const long base = (long)(blockIdx.x * (long)blockDim.x + threadIdx.x) * RPT;
    if (base >= nrows) return;

    const bool full = (base + RPT) <= (long)nrows;

    __half2 a0[NPAIR], a1[NPAIR];   // pre-activations; lanes = rows (2p, 2p+1)

    {
        const __half2 W00 = sL0[0], W01 = sL0[1], W10 = sL0[2], W11 = sL0[3];
        const __half2 B0 = sL0[4], B1 = sL0[5];

        if (full) {
            const float4* xin = reinterpret_cast<const float4*>(x) + (base >> 1);
            #pragma unroll
            for (int p = 0; p < NPAIR; p++) {
                float4 v = xin[p];                    // row 2p:(x,y), 2p+1:(z,w)
                __half2 x0 = __floats2half2_rn(v.x, v.z);
                __half2 x1 = __floats2half2_rn(v.y, v.w);
                a0[p] = __hfma2(W00, x0, __hfma2(W01, x1, B0));
                a1[p] = __hfma2(W10, x0, __hfma2(W11, x1, B1));
            }
        } else {
            #pragma unroll
            for (int p = 0; p < NPAIR; p++) {
                float x0a = 0.f, x1a = 0.f, x0b = 0.f, x1b = 0.f;
                long ra = base + 2 * p, rb = ra + 1;
                if (ra < nrows) { x0a = x[2 * ra]; x1a = x[2 * ra + 1]; }
                if (rb < nrows) { x0b = x[2 * rb]; x1b = x[2 * rb + 1]; }
                __half2 x0 = __floats2half2_rn(x0a, x0b);
                __half2 x1 = __floats2half2_rn(x1a, x1b);
                a0[p] = __hfma2(W00, x0, __hfma2(W01, x1, B0));
                a1[p] = __hfma2(W10, x0, __hfma2(W11, x1, B1));
            }
        }
    }

    // 31 fused layers, all in packed half2. Loop rolled for L0 I-cache.
    #pragma unroll 1
    for (int l = 0; l < NLAYERS - 1; l++) {
        const __half2 M00 = sM[l][0], M01 = sM[l][1];
        const __half2 M10 = sM[l][2], M11 = sM[l][3];
        const __half2 C0 = sC[l][0], C1 = sC[l][1];
        #pragma unroll
        for (int p = 0; p < NPAIR; p++) {
            __half2 t0 = tanh2(a0[p]);
            __half2 t1 = tanh2(a1[p]);
            a0[p] = __hfma2(M00, t0, __hfma2(M01, t1, C0));
            a1[p] = __hfma2(M10, t0, __hfma2(M11, t1, C1));
        }
    }

    // Final tanh + f32 output head (no f16 quantization on the result)
    const float v0 = sF[0], v1 = sF[1], co = sF[2];

    float o[RPT];
    #pragma unroll
    for (int p = 0; p < NPAIR; p++) {
        float2 t0 = __half22float2(tanh2(a0[p]));
        float2 t1 = __half22float2(tanh2(a1[p]));
        o[2 * p]     = fmaf(t0.x, v0, fmaf(t1.x, v1, co));
        o[2 * p + 1] = fmaf(t0.y, v0, fmaf(t1.y, v1, co));
    }

    if (full) {
        float4* op = reinterpret_cast<float4*>(out + base);
        #pragma unroll
        for (int i = 0; i < RPT / 4; i++)
            op[i] = make_float4(o[4 * i], o[4 * i + 1], o[4 * i + 2], o[4 * i + 3]);
    } else {
        #pragma unroll
        for (int r = 0; r < RPT; r++) {
            long row = base + r;
            if (row < nrows) out[row] = o[r];
        }
    }
}

extern "C" void kernel_launch(void* const* d_in, const int* in_sizes, int n_in,
                              void* d_out, int out_size) {
    const float* x     = (const float*)d_in[0];
    const float* W     = (const float*)d_in[1];
    const float* b     = (const float*)d_in[2];
    const float* scale = (const float*)d_in[3];
    const float* shift = (const float*)d_in[4];
    const float* Wo    = (const float*)d_in[5];
    const float* bo    = (const float*)d_in[6];
    float* out = (float*)d_out;

    const int nrows = in_sizes[0] / 2;
    const int threads = 256;
    const long total_threads = (nrows + RPT - 1) / RPT;
    const int blocks = (int)((total_threads + threads - 1) / threads);

    fraud_kernel<<<blocks, threads>>>(x, W, b, scale, shift, Wo, bo, out, nrows);
}